// round 16
// baseline (speedup 1.0000x reference)
#include <cuda_runtime.h>
#include <cstddef>

#define BB       32
#define LL       32768
#define CC       128
#define KK       64
#define PADL     31          // SAME, K even: out[t] = sum_k x[t+k-31] * w[k]

#define CH       64          // channels per CTA (half of CC)
#define CP       32          // channel pairs per CTA
#define TL       64          // output rows per CTA
#define ROWS     128         // staged x rows: [t0-31, t0+96]
#define NTHREADS 128
#define TSUB     4
#define TT       16          // outputs per thread
#define NTILE    8           // 2-output Winograd tiles per thread
#define NJ       32          // tap chunks (K/2)

#define SMEM_X_F (ROWS * CH)                     // 8192 floats = 32 KB
#define SMEM_G_F (NJ * CP * 2)                   // 2048 floats = 8 KB per array
#define SMEM_BYTES ((SMEM_X_F + 3 * SMEM_G_F) * 4)   // 57344 B -> 4 CTAs/SM (224 KB)

typedef unsigned long long ull;

// Blackwell packed f32x2 ops.
__device__ __forceinline__ ull ffma2(ull a, ull b, ull c) {
    ull d;
    asm("fma.rn.f32x2 %0, %1, %2, %3;" : "=l"(d) : "l"(a), "l"(b), "l"(c));
    return d;
}
__device__ __forceinline__ ull sub2(ull a, ull b) {   // a - b, packed
    ull d;
    asm("sub.rn.f32x2 %0, %1, %2;" : "=l"(d) : "l"(a), "l"(b));
    return d;
}
__device__ __forceinline__ ull pack2(float lo, float hi) {
    ull r;
    asm("mov.b64 %0, {%1, %2};" : "=l"(r) : "f"(lo), "f"(hi));
    return r;
}

// tanh(x) = 1 - 2/(e^{2x}+1), 5 instructions, branch-free. abs err ~2e-7.
__device__ __forceinline__ float tanh5(float x) {
    float s = x * 2.885390082f;        // 2*log2(e)
    float t, r;
    asm("ex2.approx.f32 %0, %1;" : "=f"(t) : "f"(s));
    float d = t + 1.0f;
    asm("rcp.approx.f32 %0, %1;" : "=f"(r) : "f"(d));
    return __fmaf_rn(-2.0f, r, 1.0f);
}

__global__ __launch_bounds__(NTHREADS, 4)
void dwconv1d_tanh_wino2_kernel(const float* __restrict__ x,
                                const float* __restrict__ w,     // [K][CC]
                                const float* __restrict__ bias,  // [CC]
                                float* __restrict__ out) {
    extern __shared__ float sm[];
    float* sx  = sm;                               // [ROWS][CH]
    ull*   gsp = (ull*)(sm + SMEM_X_F);            // [NJ][CP]: w0+w1
    ull*   g0p = gsp + NJ * CP;                    // [NJ][CP]: w0
    ull*   g1p = g0p + NJ * CP;                    // [NJ][CP]: -w1

    const int tid  = threadIdx.x;
    const int blk  = blockIdx.x;
    const int half = blk & 1;
    const int tile = (blk >> 1) & 511;             // LL/TL = 512
    const int b    = blk >> 10;
    const int t0   = tile * TL;

    // ---- stage transformed weights: per chunk j, taps (w[2j], w[2j+1]) ----
    {
        #pragma unroll
        for (int n = 0; n < (NJ * CP) / NTHREADS; n++) {   // 8 iters
            int idx = tid + n * NTHREADS;
            int j   = idx >> 5;
            int c   = idx & 31;
            const float2* wr = (const float2*)w + half * CP + c;  // row = CC/2 pairs
            float2 w0 = wr[(size_t)(2 * j) * (CC / 2)];
            float2 w1 = wr[(size_t)(2 * j + 1) * (CC / 2)];
            gsp[idx] = pack2(w0.x + w1.x, w0.y + w1.y);
            g0p[idx] = pack2(w0.x, w0.y);
            g1p[idx] = pack2(-w1.x, -w1.y);
        }
    }

    // ---- stage x half-rows [t0-31, t0+97), zero-padded ----
    {
        const int base = t0 - PADL;
        const float4* xsrc = (const float4*)(x + (size_t)b * LL * CC); // row = 32 f4
        float4*       xdst = (float4*)sx;                              // row = 16 f4
        #pragma unroll
        for (int n = 0; n < (SMEM_X_F / 4) / NTHREADS; n++) {   // 16 iters
            int idx = tid + n * NTHREADS;        // 0..2047
            int r   = idx >> 4;
            int col = idx & 15;
            int g   = base + r;
            float4 v = make_float4(0.f, 0.f, 0.f, 0.f);
            if ((unsigned)g < (unsigned)LL)
                v = xsrc[(size_t)g * 32 + half * 16 + col];
            xdst[idx] = v;
        }
    }
    __syncthreads();

    const int c2    = tid & (CP - 1);
    const int ts    = tid >> 5;          // 0..3 (warp-uniform)
    const int jbase = ts * TT;

    const ull* X  = ((const ull*)sx) + (size_t)jbase * CP + c2;  // X[r*CP] = row jbase+r
    const ull* GS = gsp + c2;
    const ull* G0 = g0p + c2;
    const ull* G1 = g1p + c2;

    // m-domain accumulators; bias folded into M1 (o0=M1+M2, o1=M1+M3).
    const float2 bv = ((const float2*)bias)[half * CP + c2];
    const ull bpair = pack2(bv.x, bv.y);
    ull M1[NTILE], M2[NTILE], M3[NTILE];
    #pragma unroll
    for (int t = 0; t < NTILE; t++) { M1[t] = bpair; M2[t] = 0ull; M3[t] = 0ull; }

    // Rolling windows over chunk j:
    //   Dw[(2j+r)&15] = x[jbase+2j+r] - x[jbase+2j+r+1], r = 0..15
    //   xodd[(j+i)&7] = x[jbase+2(j+i)+1],               i = 0..7
    //   xe            = x[jbase+2j+16]
    ull Dw[16], xodd[NTILE], xe;
    {
        ull prev = X[0];
        #pragma unroll
        for (int r = 0; r < 16; r++) {
            ull cur = X[(r + 1) * CP];
            Dw[r] = sub2(prev, cur);
            if ((r & 1) == 0) xodd[r >> 1] = cur;   // cur = x[jbase+r+1], r even
            prev = cur;
        }
        xe = prev;                                   // x[jbase+16]
    }

    #pragma unroll
    for (int j = 0; j < NJ; j++) {
        ull g_s = GS[j * CP];
        ull g_0 = G0[j * CP];
        ull g_1 = G1[j * CP];

        #pragma unroll
        for (int t = 0; t < NTILE; t++) {
            M1[t] = ffma2(xodd[(j + t) & (NTILE - 1)], g_s, M1[t]);   // d1*(w0+w1)
            M2[t] = ffma2(Dw[(2 * j + 2 * t) & 15],     g_0, M2[t]);  // (d0-d1)*w0
            M3[t] = ffma2(Dw[(2 * j + 2 * t + 1) & 15], g_1, M3[t]);  // (d1-d2)*(-w1)
        }

        if (j < NJ - 1) {                      // advance windows (compile-time guard)
            ull xa = X[(2 * j + 17) * CP];     // odd row
            ull xb = X[(2 * j + 18) * CP];     // even row (max 2*30+18+jbase=126 < 128)
            Dw[(2 * j + 16) & 15] = sub2(xe, xa);
            Dw[(2 * j + 17) & 15] = sub2(xa, xb);
            xodd[j & (NTILE - 1)] = xa;
            xe = xb;
        }
    }

    // ---- inverse transform + tanh + store ----
    float2* outp = (float2*)out;                       // row stride CC/2 = 64
    const size_t ob = ((size_t)b * LL + t0 + jbase) * 64 + half * CP + c2;
    #pragma unroll
    for (int t = 0; t < NTILE; t++) {
        float2 m1 = *(float2*)&M1[t];
        float2 m2 = *(float2*)&M2[t];
        float2 m3 = *(float2*)&M3[t];
        outp[ob + (size_t)(2 * t) * 64] =
            make_float2(tanh5(m1.x + m2.x), tanh5(m1.y + m2.y));
        outp[ob + (size_t)(2 * t + 1) * 64] =
            make_float2(tanh5(m1.x + m3.x), tanh5(m1.y + m3.y));
    }
}

extern "C" void kernel_launch(void* const* d_in, const int* in_sizes, int n_in,
                              void* d_out, int out_size) {
    const float* x    = (const float*)d_in[0];
    const float* w    = (const float*)d_in[1];
    const float* bias = (const float*)d_in[2];
    float*       out  = (float*)d_out;

    cudaFuncSetAttribute(dwconv1d_tanh_wino2_kernel,
                         cudaFuncAttributeMaxDynamicSharedMemorySize, SMEM_BYTES);

    // grid: b (32) x tile (512) x half (2)
    dwconv1d_tanh_wino2_kernel<<<BB * (LL / TL) * 2, NTHREADS, SMEM_BYTES>>>(x, w, bias, out);
}